// round 7
// baseline (speedup 1.0000x reference)
#include <cuda_runtime.h>

// LFQ: z [4,14,32,32] f32. Codebook = all +-1 bit patterns -> T=0.01 softmax
// factorizes per bit. With em = expf(-400|z_d|): pc=1/(1+em), po=em*pc, flip
// ratio po/pc = em exactly. A bit is "soft" only when em > 0 in fp32, so a
// token has only 2^nsoft (~8) nonzero codes -> enumerate and scatter into a
// u64 fixed-point histogram (integer atomics commute => bit-deterministic).
//
// Single persistent kernel (148 blocks = 1 CTA/SM, co-resident => grid spin
// barrier is safe): zero -> barrier -> token+marking -> barrier -> reduce.
//
// Output (f32): quantized[57344], commit, entropy_loss, usage, idx_flat[4096].

#define N_TOK 4096
#define DIM   14
#define HW    1024
#define NE    16384
#define QELEMS (N_TOK * DIM)       // 57344
#define FIXSCALE 1099511627776.0   // 2^40
#define FULLM 0xffffffffu
#define NBLK 148
#define NTHR 128
#define NTOT (NBLK * NTHR)         // 18944

__device__ unsigned long long g_hist[NE];
__device__ unsigned int       g_bitset[2048];
__device__ float              g_wcom[128];
__device__ float              g_went[128];
__device__ float              g_sae[NBLK];
__device__ float              g_scom[NBLK];
__device__ float              g_sent[NBLK];
__device__ int                g_scnt[NBLK];
__device__ unsigned int       g_bar0, g_bar1, g_ticket;   // reset by last block

// ---------------------------------------------------------------------------
__device__ __forceinline__ void grid_barrier(unsigned int* bar) {
    __syncthreads();
    if (threadIdx.x == 0) {
        __threadfence();                       // release prior writes
        atomicAdd(bar, 1u);
        while (*(volatile unsigned int*)bar < (unsigned)NBLK) { }
    }
    __syncthreads();
    __threadfence();                           // acquire
}

__device__ __forceinline__ void emit_subsets_strided(
    unsigned m, float pbase, unsigned idx, const float* __restrict__ ratio,
    unsigned start, unsigned stride)
{
    unsigned total = 1u << __popc(m);
    for (unsigned s = start; s < total; s += stride) {
        float p = pbase;
        unsigned code = idx;
        unsigned sb = s;
        #pragma unroll
        for (int d = 0; d < DIM; d++) {
            if ((m >> d) & 1u) {
                if (sb & 1u) { p *= ratio[d]; code ^= (1u << d); }
                sb >>= 1u;
            }
        }
        unsigned long long f = __double2ull_rn((double)p * FIXSCALE);
        if (f) atomicAdd(&g_hist[code], f);
    }
}

// ---------------------------------------------------------------------------
__global__ void __launch_bounds__(NTHR, 1)
k_all(const float* __restrict__ z, const int* __restrict__ used,
      float* __restrict__ out) {
    int blk = blockIdx.x;
    int tid = threadIdx.x;
    int gt  = blk * NTHR + tid;

    __shared__ unsigned s_bs[2048];
    __shared__ float reda[NTHR], redc[NTHR], rede[NTHR];
    __shared__ int   redn[NTHR];

    // ---- phase 0: zero scratch -------------------------------------------
    if (gt < NE)   g_hist[gt]   = 0ull;
    if (gt < 2048) g_bitset[gt] = 0u;

    grid_barrier(&g_bar0);

    // ---- phase 1 ----------------------------------------------------------
    if (blk < 32) {
        // token work: 128 warps, thread = token
        int lane = tid & 31;
        int wg = blk * 4 + (tid >> 5);     // 0..127
        int t  = wg * 32 + lane;
        int b  = t >> 10;
        int hw = t & 1023;
        const float* zp = z   + b * (DIM * HW) + hw;
        float*       qp = out + b * (DIM * HW) + hw;

        float com = 0.f, ent = 0.f, pbase = 1.f;
        unsigned idx = 0u, mask = 0u;
        float ratio[DIM];

        #pragma unroll
        for (int d = 0; d < DIM; d++) {
            float zv = zp[d * HW];
            float q  = (zv > 0.f) ? 1.f : -1.f;
            qp[d * HW] = q;
            float df = zv - q;
            com += df * df;
            if (zv > 0.f) idx |= (1u << d);

            float ax = 400.f * fabsf(zv);
            float em = expf(-ax);              // == flip ratio
            float pc = 1.f / (1.f + em);
            float po = em * pc;
            pbase *= pc;
            ratio[d] = em;
            if (po > 0.f) mask |= (1u << d);

            ent += log1pf(em) + po * ax;
        }

        out[QELEMS + 3 + t] = (float)idx;
        atomicOr(&g_bitset[idx >> 5], 1u << (idx & 31u));

        #pragma unroll
        for (int o = 16; o; o >>= 1) {
            com += __shfl_down_sync(FULLM, com, o);
            ent += __shfl_down_sync(FULLM, ent, o);
        }
        if (lane == 0) { g_wcom[wg] = com; g_went[wg] = ent; }

        unsigned nsoft = __popc(mask);
        if (nsoft < 6)
            emit_subsets_strided(mask, pbase, idx, ratio, 0u, 1u);

        unsigned heavy = __ballot_sync(FULLM, nsoft >= 6);
        while (heavy) {
            int L = __ffs(heavy) - 1;
            heavy &= heavy - 1u;
            unsigned hm   = __shfl_sync(FULLM, mask,  L);
            float    hp   = __shfl_sync(FULLM, pbase, L);
            unsigned hidx = __shfl_sync(FULLM, idx,   L);
            float hr[DIM];
            #pragma unroll
            for (int d = 0; d < DIM; d++) hr[d] = __shfl_sync(FULLM, ratio[d], L);
            emit_subsets_strided(hm, hp, hidx, hr, (unsigned)lane, 32u);
        }
    } else {
        // ring-buffer marking: used[4096:65536) = 61440 entries,
        // 116 blocks x 128 thr = 14848 marking threads, strided.
        for (int i = tid; i < 2048; i += NTHR) s_bs[i] = 0u;
        __syncthreads();

        int m = (blk - 32) * NTHR + tid;
        unsigned curw = 0xffffffffu, curm = 0u;
        for (int k = m; k < 65536 - N_TOK; k += 14848) {
            unsigned v = ((unsigned)used[N_TOK + k]) & 65535u;
            unsigned w = v >> 5, mm = 1u << (v & 31u);
            if (w == curw) curm |= mm;
            else {
                if (curw != 0xffffffffu) atomicOr(&s_bs[curw], curm);
                curw = w; curm = mm;
            }
        }
        if (curw != 0xffffffffu) atomicOr(&s_bs[curw], curm);
        __syncthreads();

        for (int i = tid; i < 2048; i += NTHR) {
            unsigned v = s_bs[i];
            if (v) atomicOr(&g_bitset[i], v);
        }
    }

    grid_barrier(&g_bar1);

    // ---- phase 2: reduce --------------------------------------------------
    float ae = 0.f;
    if (gt < NE) {
        unsigned long long hv = g_hist[gt];
        if (hv) {
            float avg = (float)((double)hv * (1.0 / FIXSCALE) * (1.0 / 4096.0));
            ae = -avg * logf(avg + 1e-5f);
        }
    }
    int   cnt = (gt < 2048) ? __popc(g_bitset[gt]) : 0;
    float cs  = (gt < 128) ? g_wcom[gt] : 0.f;
    float es  = (gt >= 128 && gt < 256) ? g_went[gt - 128] : 0.f;

    reda[tid] = ae; redn[tid] = cnt; redc[tid] = cs; rede[tid] = es;
    __syncthreads();
    for (int o = 64; o; o >>= 1) {
        if (tid < o) {
            reda[tid] += reda[tid + o];
            redn[tid] += redn[tid + o];
            redc[tid] += redc[tid + o];
            rede[tid] += rede[tid + o];
        }
        __syncthreads();
    }
    if (tid == 0) {
        g_sae[blk]  = reda[0];
        g_scnt[blk] = redn[0];
        g_scom[blk] = redc[0];
        g_sent[blk] = rede[0];
    }

    __shared__ int s_last;
    __threadfence();
    if (tid == 0) s_last = (atomicAdd(&g_ticket, 1u) == (unsigned)(NBLK - 1));
    __syncthreads();

    if (s_last) {
        __threadfence();
        float a = 0.f, c2 = 0.f, e2 = 0.f;
        int   c = 0;
        if (tid < NBLK) { a = g_sae[tid]; c = g_scnt[tid]; c2 = g_scom[tid]; e2 = g_sent[tid]; }
        if (tid + NTHR < NBLK) {    // slots 128..147 folded into lanes 0..19
            a  += g_sae[tid + NTHR];  c  += g_scnt[tid + NTHR];
            c2 += g_scom[tid + NTHR]; e2 += g_sent[tid + NTHR];
        }
        reda[tid] = a; redn[tid] = c; redc[tid] = c2; rede[tid] = e2;
        __syncthreads();
        for (int o = 64; o; o >>= 1) {
            if (tid < o) {
                reda[tid] += reda[tid + o];
                redn[tid] += redn[tid + o];
                redc[tid] += redc[tid + o];
                rede[tid] += rede[tid + o];
            }
            __syncthreads();
        }
        if (tid == 0) {
            float commit   = 0.25f * redc[0] / (float)QELEMS;
            float sample_e = rede[0] / (float)N_TOK;
            out[QELEMS + 0] = commit;
            out[QELEMS + 1] = 0.1f * (sample_e - reda[0]);
            out[QELEMS + 2] = (float)redn[0] / (float)NE;
            // reset counters for the next graph replay
            *(volatile unsigned int*)&g_bar0   = 0u;
            *(volatile unsigned int*)&g_bar1   = 0u;
            *(volatile unsigned int*)&g_ticket = 0u;
        }
    }
}

// ---------------------------------------------------------------------------
extern "C" void kernel_launch(void* const* d_in, const int* in_sizes, int n_in,
                              void* d_out, int out_size) {
    const float* z    = (const float*)d_in[0];
    const int*   used = (const int*)d_in[2];
    float*       out  = (float*)d_out;

    k_all<<<NBLK, NTHR>>>(z, used, out);
}